// round 2
// baseline (speedup 1.0000x reference)
#include <cuda_runtime.h>
#include <cuda_bf16.h>

// Problem shapes (fixed by the reference):
//   xq      [1, 8, 128, 128]  float32   (in_sizes[0] = 131072)
//   xk      [1, 1, 128, 128]  float32   (in_sizes[1] = 16384)
//   rot_mat [1, 128, 128, 128] float32  (in_sizes[2] = 2097152)
// Output: xq_out (131072 floats) followed by xk_out (16384 floats).
//
// out[n, s, d] = sum_h x[n, s, h] * R[s, h, d]

#define SEQ_LEN   128
#define HEAD_DIM  128
#define N_HEADS   9      // 8 q heads + 1 k head, all rotated by the same R[s]
#define THREADS   256
#define N_HOFF    8      // h-dimension split factor (THREADS / 32)

__global__ __launch_bounds__(THREADS, 1)
void rotary_kernel(const float* __restrict__ xq,
                   const float* __restrict__ xk,
                   const float* __restrict__ R,
                   float* __restrict__ out)
{
    const int s   = blockIdx.x;          // sequence position
    const int tid = threadIdx.x;
    const int d4   = tid & 31;           // which float4 column group (d = 4*d4 .. 4*d4+3)
    const int hoff = tid >> 5;           // h-phase: handles h = hoff, hoff+8, ..., hoff+120

    __shared__ float xs[N_HEADS][HEAD_DIM];                 // 4.5 KB
    __shared__ float partial[N_HOFF][N_HEADS][HEAD_DIM];    // 36 KB

    // ---- Stage x rows for this s into smem (coalesced over h) ----
    for (int idx = tid; idx < N_HEADS * HEAD_DIM; idx += THREADS) {
        const int n = idx >> 7;          // idx / 128
        const int h = idx & 127;         // idx % 128
        float v;
        if (n < 8)
            v = xq[(size_t)n * (SEQ_LEN * HEAD_DIM) + (size_t)s * HEAD_DIM + h];
        else
            v = xk[(size_t)s * HEAD_DIM + h];
        xs[n][h] = v;
    }
    __syncthreads();

    // ---- Stream R[s] once; each 16B chunk reused for all 9 heads ----
    const float4* __restrict__ R4 =
        reinterpret_cast<const float4*>(R + (size_t)s * HEAD_DIM * HEAD_DIM);

    float4 acc[N_HEADS];
#pragma unroll
    for (int n = 0; n < N_HEADS; n++)
        acc[n] = make_float4(0.f, 0.f, 0.f, 0.f);

#pragma unroll 4
    for (int k = 0; k < HEAD_DIM / N_HOFF; k++) {   // 16 iterations
        const int h = hoff + k * N_HOFF;
        const float4 r = R4[h * (HEAD_DIM / 4) + d4];   // coalesced: warp covers 512B row
#pragma unroll
        for (int n = 0; n < N_HEADS; n++) {
            const float xv = xs[n][h];                  // warp-broadcast LDS
            acc[n].x = fmaf(xv, r.x, acc[n].x);
            acc[n].y = fmaf(xv, r.y, acc[n].y);
            acc[n].z = fmaf(xv, r.z, acc[n].z);
            acc[n].w = fmaf(xv, r.w, acc[n].w);
        }
    }

    // ---- Write h-phase partials to smem ----
#pragma unroll
    for (int n = 0; n < N_HEADS; n++) {
        float4* p = reinterpret_cast<float4*>(&partial[hoff][n][d4 * 4]);
        *p = acc[n];
    }
    __syncthreads();

    // ---- Reduce the 8 partials and store (coalesced over d) ----
    for (int idx = tid; idx < N_HEADS * HEAD_DIM; idx += THREADS) {
        const int n = idx >> 7;
        const int d = idx & 127;
        float sum = 0.f;
#pragma unroll
        for (int p = 0; p < N_HOFF; p++)
            sum += partial[p][n][d];

        if (n < 8)
            out[(size_t)n * (SEQ_LEN * HEAD_DIM) + (size_t)s * HEAD_DIM + d] = sum;
        else
            out[(size_t)8 * (SEQ_LEN * HEAD_DIM) + (size_t)s * HEAD_DIM + d] = sum;
    }
}

extern "C" void kernel_launch(void* const* d_in, const int* in_sizes, int n_in,
                              void* d_out, int out_size)
{
    const float* xq = (const float*)d_in[0];
    const float* xk = (const float*)d_in[1];
    const float* R  = (const float*)d_in[2];
    float* out      = (float*)d_out;

    rotary_kernel<<<SEQ_LEN, THREADS>>>(xq, xk, R, out);
}